// round 1
// baseline (speedup 1.0000x reference)
#include <cuda_runtime.h>
#include <cuda_bf16.h>

// Problem constants
#define HW   16384      // 128*128 pixels
#define C    256        // feature dim
#define NFG  4096
#define NBG  12288
#define MT   64         // pixel tile (rows)
#define NT   64         // collection tile (cols)
#define KC   16         // k chunk
#define TOPK 20

// Scratch for normalized features (static device globals — no allocation)
__device__ float g_sN[HW * C];     // 16 MB, row-major [pixel][c]
__device__ float g_fgN[NFG * C];   // 4 MB
__device__ float g_bgN[NBG * C];   // 12 MB

// ---------------------------------------------------------------------------
// Normalize pixel features: input [C, HW] (channel-major), output [HW, C]
// ---------------------------------------------------------------------------
__global__ void norm_s_kernel(const float* __restrict__ s) {
    int p = blockIdx.x * blockDim.x + threadIdx.x;   // pixel id, coalesced over lanes
    float ss = 0.f;
#pragma unroll 8
    for (int c = 0; c < C; c++) {
        float v = s[c * HW + p];
        ss += v * v;
    }
    float sc = 1.f / fmaxf(sqrtf(ss), 1e-12f);
#pragma unroll 8
    for (int c = 0; c < C; c++) {
        g_sN[p * C + c] = s[c * HW + p] * sc;
    }
}

// ---------------------------------------------------------------------------
// Normalize collection rows: [R, 256] row-major in, row-major out. Warp/row.
// ---------------------------------------------------------------------------
__global__ void norm_rows_kernel(const float* __restrict__ x, int R, int isBg) {
    float* __restrict__ y = isBg ? g_bgN : g_fgN;
    int gwarp = (blockIdx.x * blockDim.x + threadIdx.x) >> 5;
    int lane  = threadIdx.x & 31;
    int nwarp = (gridDim.x * blockDim.x) >> 5;
    for (int r = gwarp; r < R; r += nwarp) {
        const float* xr = x + (size_t)r * C;
        float v[8];
        float ss = 0.f;
#pragma unroll
        for (int j = 0; j < 8; j++) {
            v[j] = xr[lane + 32 * j];
            ss += v[j] * v[j];
        }
#pragma unroll
        for (int o = 16; o; o >>= 1) ss += __shfl_xor_sync(0xffffffffu, ss, o);
        float sc = 1.f / fmaxf(sqrtf(ss), 1e-12f);
        float* yr = y + (size_t)r * C;
#pragma unroll
        for (int j = 0; j < 8; j++) yr[lane + 32 * j] = v[j] * sc;
    }
}

// ---------------------------------------------------------------------------
// Fused GEMM + streaming top-K.
// Block: 256 threads, owns MT=64 pixels. Loops over all N collection vectors
// in NT=64 tiles. Each thread computes a 4x4 micro-tile (16x16 thread grid).
// After each tile, row-owner threads (tid<64) merge 64 candidates into a
// 20-entry top list kept in shared memory.
//
// Dynamic smem layout (floats):
//   As  [C][MT]        k-major pixel tile (loaded once)     256*64 = 16384
//   Bs  [KC][NT]       k-major collection chunk              16*64 = 1024
//   Sim [MT][68]       per-tile similarity scores            64*68 = 4352
//   Top [MT][21]       top-K lists (stride 21: conflict-free) 64*21 = 1344
// total = 23104 floats = 92416 B  -> 2 CTAs/SM
// ---------------------------------------------------------------------------
#define SIM_LD 68
#define TOP_LD 21
#define SMEM_FLOATS (C * MT + KC * NT + MT * SIM_LD + MT * TOP_LD)
#define SMEM_BYTES  (SMEM_FLOATS * 4)

__global__ __launch_bounds__(256, 2) void match_topk_kernel(float* __restrict__ out) {
    extern __shared__ float sm[];
    float* As  = sm;                        // [C][MT]
    float* Bs  = As + C * MT;               // [KC][NT]
    float* Sim = Bs + KC * NT;              // [MT][SIM_LD]
    float* Top = Sim + MT * SIM_LD;         // [MT][TOP_LD]

    int tid = threadIdx.x;
    int bid = blockIdx.x;                   // 0..511 : bg blocks first (3x work)
    bool isBg = bid < (HW / MT);
    int mb = isBg ? bid : bid - (HW / MT);
    const float* __restrict__ Bmat = isBg ? g_bgN : g_fgN;
    int N = isBg ? NBG : NFG;
    float* __restrict__ o = out + (isBg ? HW : 0) + mb * MT;

    // ---- Stage A (pixel tile), transposed to k-major ----
    const float4* Ag = (const float4*)(g_sN + (size_t)mb * MT * C);
    for (int i = tid; i < MT * (C / 4); i += 256) {
        int m  = i / (C / 4);
        int k4 = i % (C / 4);
        float4 v = Ag[i];
        As[(k4 * 4 + 0) * MT + m] = v.x;
        As[(k4 * 4 + 1) * MT + m] = v.y;
        As[(k4 * 4 + 2) * MT + m] = v.z;
        As[(k4 * 4 + 3) * MT + m] = v.w;
    }

    // ---- Init top lists ----
    float minv = -1e30f;
    int   minIdx = 0;
    if (tid < MT) {
        float* tl = Top + tid * TOP_LD;
#pragma unroll
        for (int q = 0; q < TOPK; q++) tl[q] = -1e30f;
    }
    __syncthreads();

    int tc = tid & 15;     // col group
    int tr = tid >> 4;     // row group

    for (int nt = 0; nt < N / NT; nt++) {
        float acc[4][4];
#pragma unroll
        for (int i = 0; i < 4; i++)
#pragma unroll
            for (int j = 0; j < 4; j++) acc[i][j] = 0.f;

        const float* __restrict__ Bg = Bmat + (size_t)(nt * NT) * C;

        for (int kt = 0; kt < C / KC; kt++) {
            // load Bs[KC][NT]: 256 threads, one float4 each
            {
                int n  = tid & 63;
                int kg = tid >> 6;   // 0..3
                float4 v = *(const float4*)&Bg[n * C + kt * KC + kg * 4];
                Bs[(kg * 4 + 0) * NT + n] = v.x;
                Bs[(kg * 4 + 1) * NT + n] = v.y;
                Bs[(kg * 4 + 2) * NT + n] = v.z;
                Bs[(kg * 4 + 3) * NT + n] = v.w;
            }
            __syncthreads();
#pragma unroll
            for (int kk = 0; kk < KC; kk++) {
                float4 a = *(const float4*)(As + (kt * KC + kk) * MT + tr * 4);
                float4 b = *(const float4*)(Bs + kk * NT + tc * 4);
                acc[0][0] += a.x * b.x; acc[0][1] += a.x * b.y; acc[0][2] += a.x * b.z; acc[0][3] += a.x * b.w;
                acc[1][0] += a.y * b.x; acc[1][1] += a.y * b.y; acc[1][2] += a.y * b.z; acc[1][3] += a.y * b.w;
                acc[2][0] += a.z * b.x; acc[2][1] += a.z * b.y; acc[2][2] += a.z * b.z; acc[2][3] += a.z * b.w;
                acc[3][0] += a.w * b.x; acc[3][1] += a.w * b.y; acc[3][2] += a.w * b.z; acc[3][3] += a.w * b.w;
            }
            __syncthreads();
        }

        // ---- dump tile to smem ----
#pragma unroll
        for (int i = 0; i < 4; i++)
#pragma unroll
            for (int j = 0; j < 4; j++)
                Sim[(tr * 4 + i) * SIM_LD + (tc * 4 + j)] = acc[i][j];
        __syncthreads();

        // ---- streaming top-K merge: one thread per pixel row ----
        if (tid < MT) {
            float* tl = Top + tid * TOP_LD;
            const float* srow = Sim + tid * SIM_LD;
            for (int j = 0; j < NT; j++) {
                float v = srow[j];
                if (v > minv) {
                    tl[minIdx] = v;
                    // recompute min of the 20-entry list
                    float mn = tl[0]; int mi = 0;
#pragma unroll
                    for (int q = 1; q < TOPK; q++) {
                        float t = tl[q];
                        if (t < mn) { mn = t; mi = q; }
                    }
                    minv = mn; minIdx = mi;
                }
            }
        }
        __syncthreads();   // protect Sim/Bs reuse next tile
    }

    // ---- mean of top-K ----
    if (tid < MT) {
        float* tl = Top + tid * TOP_LD;
        float s = 0.f;
#pragma unroll
        for (int q = 0; q < TOPK; q++) s += tl[q];
        o[tid] = s * (1.0f / TOPK);
    }
}

// ---------------------------------------------------------------------------
// kernel_launch: inputs per metadata order: s_feat, fg_feats, bg_feats
// out: [fg_score(16384) | bg_score(16384)] float32
// ---------------------------------------------------------------------------
extern "C" void kernel_launch(void* const* d_in, const int* in_sizes, int n_in,
                              void* d_out, int out_size) {
    const float* s  = (const float*)d_in[0];
    const float* fg = (const float*)d_in[1];
    const float* bg = (const float*)d_in[2];
    float* out = (float*)d_out;

    cudaFuncSetAttribute(match_topk_kernel,
                         cudaFuncAttributeMaxDynamicSharedMemorySize, SMEM_BYTES);

    norm_s_kernel<<<HW / 128, 128>>>(s);
    norm_rows_kernel<<<64, 256>>>(fg, NFG, 0);
    norm_rows_kernel<<<64, 256>>>(bg, NBG, 1);
    match_topk_kernel<<<(HW / MT) * 2, 256, SMEM_BYTES>>>(out);
}

// round 3
// speedup vs baseline: 2.0234x; 2.0234x over previous
#include <cuda_runtime.h>
#include <cstdint>

// ---------------------------------------------------------------- constants
#define HW    16384
#define C     256
#define NFG   4096
#define NBG   12288
#define TOPK  20
#define MT    128
#define NT    128
#define FG_TILES (NFG / NT)          // 32
#define NTILES   ((NFG + NBG) / NT)  // 128
#define NCHUNKS  (NTILES * 8)        // k-chunks of 32 over all tiles

#define APAD 260                     // A row stride (floats): (4m+k)%32 distinct
#define BPAD 36                      // B row stride (floats)

#define A_FLOATS (MT * APAD)                 // 33280
#define B_FLOATS (NT * BPAD)                 // 4608 per buffer
#define MG_FLOATS (256 * TOPK)               // 5120
#define SMEM_FLOATS (A_FLOATS + 2 * B_FLOATS + MG_FLOATS)
#define SMEM_BYTES  (SMEM_FLOATS * 4)        // 190464

// normalized (tf32-rounded) features — static device scratch
__device__ float g_sN[HW * C];
__device__ float g_fgN[NFG * C];
__device__ float g_bgN[NBG * C];

// ---------------------------------------------------------------- helpers
__device__ __forceinline__ float to_tf32(float x) {
    uint32_t u; asm("cvt.rna.tf32.f32 %0, %1;" : "=r"(u) : "f"(x));
    return __uint_as_float(u);
}
__device__ __forceinline__ uint32_t smem_u32(const void* p) {
    uint32_t a;
    asm("{ .reg .u64 t; cvta.to.shared.u64 t, %1; cvt.u32.u64 %0, t; }"
        : "=r"(a) : "l"(p));
    return a;
}
__device__ __forceinline__ void cp_async16(uint32_t dst, const void* src) {
    asm volatile("cp.async.cg.shared.global [%0], [%1], 16;" :: "r"(dst), "l"(src));
}
__device__ __forceinline__ void cp_commit() {
    asm volatile("cp.async.commit_group;" ::: "memory");
}
__device__ __forceinline__ void cp_wait0() {
    asm volatile("cp.async.wait_group 0;" ::: "memory");
}
__device__ __forceinline__ void mma_tf32(float* d, const uint32_t* a,
                                         uint32_t b0, uint32_t b1) {
    asm volatile(
        "mma.sync.aligned.m16n8k8.row.col.f32.tf32.tf32.f32 "
        "{%0,%1,%2,%3}, {%4,%5,%6,%7}, {%8,%9}, {%0,%1,%2,%3};"
        : "+f"(d[0]), "+f"(d[1]), "+f"(d[2]), "+f"(d[3])
        : "r"(a[0]), "r"(a[1]), "r"(a[2]), "r"(a[3]), "r"(b0), "r"(b1));
}

// ---------------------------------------------------------------- normalize
__global__ void norm_s_kernel(const float* __restrict__ s) {
    int p = blockIdx.x * blockDim.x + threadIdx.x;
    float ss = 0.f;
#pragma unroll 8
    for (int c = 0; c < C; c++) { float v = s[c * HW + p]; ss += v * v; }
    float sc = 1.f / fmaxf(sqrtf(ss), 1e-12f);
#pragma unroll 8
    for (int c = 0; c < C; c++)
        g_sN[p * C + c] = to_tf32(s[c * HW + p] * sc);
}

__global__ void norm_rows_kernel(const float* __restrict__ x, int R, int isBg) {
    float* __restrict__ y = isBg ? g_bgN : g_fgN;
    int gwarp = (blockIdx.x * blockDim.x + threadIdx.x) >> 5;
    int lane  = threadIdx.x & 31;
    int nwarp = (gridDim.x * blockDim.x) >> 5;
    for (int r = gwarp; r < R; r += nwarp) {
        const float* xr = x + (size_t)r * C;
        float v[8]; float ss = 0.f;
#pragma unroll
        for (int j = 0; j < 8; j++) { v[j] = xr[lane + 32 * j]; ss += v[j] * v[j]; }
#pragma unroll
        for (int o = 16; o; o >>= 1) ss += __shfl_xor_sync(0xffffffffu, ss, o);
        float sc = 1.f / fmaxf(sqrtf(ss), 1e-12f);
        float* yr = y + (size_t)r * C;
#pragma unroll
        for (int j = 0; j < 8; j++) yr[lane + 32 * j] = to_tf32(v[j] * sc);
    }
}

// ---------------------------------------------------------------- main kernel
// 256 threads = 8 warps: mwarp = wid>>1 (4 M groups of 32 rows),
// nwarp = wid&1 (2 N groups of 64 cols). Warp tile 32x64 via m16n8k8 tf32.
__global__ __launch_bounds__(256, 1) void gemm_topk(float* __restrict__ out) {
    extern __shared__ float sm[];
    float* As  = sm;                   // [128][APAD]
    float* Bs0 = As + A_FLOATS;        // [128][BPAD]
    float* Bs1 = Bs0 + B_FLOATS;
    float* Mg  = Bs1 + B_FLOATS;       // [256][20] merge buffer

    const int tid   = threadIdx.x;
    const int lane  = tid & 31;
    const int wid   = tid >> 5;
    const int mwarp = wid >> 1;
    const int nwarp = wid & 1;
    const int g4    = lane >> 2;       // groupID
    const int t4    = lane & 3;        // thread in group
    const int mb    = blockIdx.x;

    // ---- stage A (once) ----
    {
        const float* Ag = g_sN + (size_t)mb * MT * C;
#pragma unroll
        for (int j = 0; j < 32; j++) {
            int idx = tid + j * 256;           // 8192 float4 total
            int r   = idx >> 6;                // 64 float4 per row
            int k4  = idx & 63;
            float4 v = *(const float4*)(Ag + r * C + k4 * 4);
            *(float4*)&As[r * APAD + k4 * 4] = v;
        }
    }

    // ---- B prefetch helper (chunk ci = tile*8 + kc) ----
    uint32_t b0a = smem_u32(Bs0), b1a = smem_u32(Bs1);
    auto issueB = [&](int ci) {
        if (ci >= NCHUNKS) return;
        int t  = ci >> 3, kc = ci & 7;
        const float* src = (t < FG_TILES ? g_fgN + (size_t)t * NT * C
                                         : g_bgN + (size_t)(t - FG_TILES) * NT * C)
                           + kc * 32;
        uint32_t sb = (ci & 1) ? b1a : b0a;
#pragma unroll
        for (int j = 0; j < 4; j++) {
            int idx = tid + j * 256;           // 1024 float4
            int n   = idx >> 3;
            int k4  = idx & 7;
            cp_async16(sb + (uint32_t)(n * BPAD + k4 * 4) * 4u,
                       src + n * C + k4 * 4);
        }
        cp_commit();
    };
    issueB(0);

    // ---- top-K state ----
    float top[4][TOPK];                // local mem (dynamic index)
    float mnv[4]; int mni[4];
#pragma unroll
    for (int p = 0; p < 4; p++) {
#pragma unroll
        for (int q = 0; q < TOPK; q++) top[p][q] = -1e30f;
        mnv[p] = -1e30f; mni[p] = 0;
    }

    float acc[2][8][4];
#pragma unroll
    for (int mt = 0; mt < 2; mt++)
#pragma unroll
        for (int nt = 0; nt < 8; nt++)
#pragma unroll
            for (int c = 0; c < 4; c++) acc[mt][nt][c] = 0.f;

    const int aRow0 = mwarp * 32 + g4;         // + mt*16, +8 for a1
    const int bRow0 = nwarp * 64 + g4;         // + nt*8

    for (int t = 0; t < NTILES; t++) {
        for (int kc = 0; kc < 8; kc++) {
            int ci = t * 8 + kc;
            cp_wait0();
            __syncthreads();
            issueB(ci + 1);
            const float* Bb = (ci & 1) ? Bs1 : Bs0;
#pragma unroll
            for (int s = 0; s < 4; s++) {
                int k0 = kc * 32 + s * 8 + t4;
                uint32_t a[2][4];
#pragma unroll
                for (int mt = 0; mt < 2; mt++) {
                    const float* ap = &As[(aRow0 + mt * 16) * APAD + k0];
                    a[mt][0] = __float_as_uint(ap[0]);
                    a[mt][1] = __float_as_uint(ap[8 * APAD]);
                    a[mt][2] = __float_as_uint(ap[4]);
                    a[mt][3] = __float_as_uint(ap[8 * APAD + 4]);
                }
#pragma unroll
                for (int nt = 0; nt < 8; nt++) {
                    const float* bp = &Bb[(bRow0 + nt * 8) * BPAD + s * 8 + t4];
                    uint32_t bb0 = __float_as_uint(bp[0]);
                    uint32_t bb1 = __float_as_uint(bp[4]);
                    mma_tf32(acc[0][nt], a[0], bb0, bb1);
                    mma_tf32(acc[1][nt], a[1], bb0, bb1);
                }
            }
        }

        // ---- top-K update from this tile's 64 finished sims ----
#pragma unroll
        for (int p = 0; p < 4; p++) {
            int mt = p >> 1, h = p & 1;
            float mx = -1e30f;
#pragma unroll
            for (int nt = 0; nt < 8; nt++) {
                mx = fmaxf(mx, acc[mt][nt][2 * h]);
                mx = fmaxf(mx, acc[mt][nt][2 * h + 1]);
            }
            if (mx > mnv[p]) {                 // rare after warm-up
#pragma unroll
                for (int nt = 0; nt < 8; nt++) {
#pragma unroll
                    for (int cc = 0; cc < 2; cc++) {
                        float v = acc[mt][nt][2 * h + cc];
                        if (v > mnv[p]) {
                            top[p][mni[p]] = v;
                            float m = top[p][0]; int mi = 0;
#pragma unroll
                            for (int q = 1; q < TOPK; q++) {
                                float tq = top[p][q];
                                if (tq < m) { m = tq; mi = q; }
                            }
                            mnv[p] = m; mni[p] = mi;
                        }
                    }
                }
            }
        }
        // reset acc
#pragma unroll
        for (int mt = 0; mt < 2; mt++)
#pragma unroll
            for (int nt = 0; nt < 8; nt++)
#pragma unroll
                for (int c = 0; c < 4; c++) acc[mt][nt][c] = 0.f;

        // ---- fg boundary: merge + reset ----
        if (t == FG_TILES - 1 || t == NTILES - 1) {
            float* obase = out + (t == FG_TILES - 1 ? 0 : HW) + mb * MT;
#pragma unroll 1
            for (int p = 0; p < 4; p++) {
#pragma unroll
                for (int q = 0; q < TOPK; q++) Mg[tid * TOPK + q] = top[p][q];
                __syncthreads();
                if (tid < 32) {
                    int mw = tid >> 3, rg = tid & 7;
                    int mt = p >> 1, h = p & 1;
                    int row = mw * 32 + mt * 16 + h * 8 + rg;
                    float best[TOPK]; float bm = -1e30f; int bi = 0;
#pragma unroll
                    for (int q = 0; q < TOPK; q++) best[q] = -1e30f;
                    for (int nw = 0; nw < 2; nw++)
                        for (int l = 0; l < 4; l++) {
                            int src = (mw * 2 + nw) * 32 + rg * 4 + l;
                            for (int q = 0; q < TOPK; q++) {
                                float v = Mg[src * TOPK + q];
                                if (v > bm) {
                                    best[bi] = v;
                                    float m = best[0]; int mi = 0;
#pragma unroll
                                    for (int qq = 1; qq < TOPK; qq++) {
                                        float tq = best[qq];
                                        if (tq < m) { m = tq; mi = qq; }
                                    }
                                    bm = m; bi = mi;
                                }
                            }
                        }
                    float ssum = 0.f;
#pragma unroll
                    for (int q = 0; q < TOPK; q++) ssum += best[q];
                    obase[row] = ssum * (1.0f / TOPK);
                }
                __syncthreads();
            }
            // reset lists for bg
#pragma unroll
            for (int p = 0; p < 4; p++) {
#pragma unroll
                for (int q = 0; q < TOPK; q++) top[p][q] = -1e30f;
                mnv[p] = -1e30f; mni[p] = 0;
            }
        }
    }
}

// ---------------------------------------------------------------- launch
extern "C" void kernel_launch(void* const* d_in, const int* in_sizes, int n_in,
                              void* d_out, int out_size) {
    const float* s  = (const float*)d_in[0];
    const float* fg = (const float*)d_in[1];
    const float* bg = (const float*)d_in[2];
    float* out = (float*)d_out;

    cudaFuncSetAttribute(gemm_topk,
                         cudaFuncAttributeMaxDynamicSharedMemorySize, SMEM_BYTES);

    norm_s_kernel<<<HW / 128, 128>>>(s);
    norm_rows_kernel<<<128, 256>>>(fg, NFG, 0);
    norm_rows_kernel<<<128, 256>>>(bg, NBG, 1);
    gemm_topk<<<HW / MT, 256, SMEM_BYTES>>>(out);
}